// round 8
// baseline (speedup 1.0000x reference)
#include <cuda_runtime.h>
#include <cuda_bf16.h>
#include <cstdint>
#include <math.h>

#define STEPS 511
#define BATCH 8
#define HID   256
#define G4    1024
#define VOCAB 32000
#define NROWS (STEPS*BATCH)   // 4088
#define NPAD  4096
#define KCAT  768             // [hi | hi/lo split] concat K

// ---------------- scratch (no allocs allowed) ----------------
__device__ float g_xp[STEPS*BATCH*G4];                // gate-interleaved: [r][unit*4+gate]
__device__ float g_h1[STEPS*BATCH*HID];
__device__ float g_h2[STEPS*BATCH*HID];
__device__ __nv_bfloat16 g_wcat[(size_t)VOCAB*KCAT];  // 49 MB  out_w split
__device__ __nv_bfloat16 g_acat[(size_t)NPAD*KCAT];   // 6.3 MB gated-h2 split
__device__ uint32_t g_f0[STEPS];                      // xp0 ready counts (target 32)
__device__ uint32_t g_f1[STEPS];                      // xp1 ready counts (target 32)
__device__ uint32_t g_fh[STEPS];                      // h1 ready counts  (target 512)

__device__ __forceinline__ float sigmoidf_(float x){ return 1.0f/(1.0f + __expf(-x)); }

__device__ __forceinline__ uint32_t smem_u32(const void* p){
  return (uint32_t)__cvta_generic_to_shared(p);
}
__device__ __forceinline__ void mbar_init_(uint32_t a, uint32_t cnt){
  asm volatile("mbarrier.init.shared.b64 [%0], %1;" :: "r"(a), "r"(cnt) : "memory");
}
__device__ __forceinline__ void mbar_expect_tx_(uint32_t a, uint32_t bytes){
  asm volatile("mbarrier.arrive.expect_tx.shared.b64 _, [%0], %1;" :: "r"(a), "r"(bytes) : "memory");
}
__device__ __forceinline__ void mbar_wait_(uint32_t a, uint32_t phase){
  asm volatile("{\n\t.reg .pred P;\n\t"
    "WL_%=:\n\t"
    "mbarrier.try_wait.parity.acquire.cta.shared::cta.b64 P, [%0], %1, 0x989680;\n\t"
    "@P bra.uni WD_%=;\n\t"
    "bra.uni WL_%=;\n\t"
    "WD_%=:\n\t}" :: "r"(a), "r"(phase) : "memory");
}
__device__ __forceinline__ uint32_t mapa_(uint32_t addr, uint32_t rank){
  uint32_t r;
  asm("mapa.shared::cluster.u32 %0, %1, %2;" : "=r"(r) : "r"(addr), "r"(rank));
  return r;
}
__device__ __forceinline__ void bulk_s2c_(uint32_t dst, uint32_t src, uint32_t bytes, uint32_t mbp){
  asm volatile("cp.async.bulk.shared::cluster.shared::cta.mbarrier::complete_tx::bytes [%0], [%1], %2, [%3];"
    :: "r"(dst), "r"(src), "r"(bytes), "r"(mbp) : "memory");
}
__device__ __forceinline__ void cluster_sync_(){
  asm volatile("barrier.cluster.arrive.aligned;" ::: "memory");
  asm volatile("barrier.cluster.wait.aligned;"   ::: "memory");
}
__device__ __forceinline__ void fence_proxy_async_(){
  asm volatile("fence.proxy.async.shared::cta;" ::: "memory");
}
__device__ __forceinline__ uint32_t ld_acq_(const uint32_t* p){
  uint32_t v;
  asm volatile("ld.acquire.gpu.global.u32 %0, [%1];" : "=r"(v) : "l"(p) : "memory");
  return v;
}
__device__ __forceinline__ void red_rel_add_(uint32_t* p){
  asm volatile("red.release.gpu.global.add.u32 [%0], 1;" :: "l"(p) : "memory");
}
__device__ __forceinline__ float4 ldcg4_(const float* p){
  float4 v;
  asm volatile("ld.global.cg.v4.f32 {%0,%1,%2,%3}, [%4];"
    : "=f"(v.x), "=f"(v.y), "=f"(v.z), "=f"(v.w) : "l"(p));
  return v;
}
__device__ __forceinline__ void cp_async16_(uint32_t saddr, const void* gaddr){
  asm volatile("cp.async.cg.shared.global [%0], [%1], 16;" :: "r"(saddr), "l"(gaddr) : "memory");
}
#define CP_COMMIT() asm volatile("cp.async.commit_group;" ::: "memory")
#define CP_WAIT1()  asm volatile("cp.async.wait_group 1;" ::: "memory")
#define CP_WAIT0()  asm volatile("cp.async.wait_group 0;" ::: "memory")

__device__ __forceinline__ void ldsm_x4_(uint32_t* r, uint32_t addr){
  asm volatile("ldmatrix.sync.aligned.m8n8.x4.shared.b16 {%0,%1,%2,%3}, [%4];"
    : "=r"(r[0]), "=r"(r[1]), "=r"(r[2]), "=r"(r[3]) : "r"(addr));
}
__device__ __forceinline__ void mma16816_(float* d, const uint32_t* a, const uint32_t* b){
  asm volatile("mma.sync.aligned.m16n8k16.row.col.f32.bf16.bf16.f32 "
    "{%0,%1,%2,%3}, {%4,%5,%6,%7}, {%8,%9}, {%0,%1,%2,%3};"
    : "+f"(d[0]), "+f"(d[1]), "+f"(d[2]), "+f"(d[3])
    : "r"(a[0]), "r"(a[1]), "r"(a[2]), "r"(a[3]), "r"(b[0]), "r"(b[1]));
}
static __device__ __forceinline__ uint32_t sw128_(uint32_t b){ return b ^ ((b >> 3) & 0x70u); }

// ============================================================
// clear pipeline flags (precedes pipe each replay, same stream)
// ============================================================
__global__ void __launch_bounds__(256) clearflags_kernel(){
  for (int i = blockIdx.x*256 + threadIdx.x; i < STEPS; i += gridDim.x*256){
    g_f0[i] = 0u; g_f1[i] = 0u; g_fh[i] = 0u;
  }
}

// ============================================================
// shared smem for the fused pipe kernel
// ============================================================
struct ScanSmem {
  float h_s[2][512];     // [phase][j*64 + b*32 + u]
  float stg[2][64];      // [phase][b*32 + u]
  unsigned long long mbar[2];
};
struct Xp0Smem { float Hs[8][128]; int cap[8]; };
struct Xp1Smem { float Hs[8][256]; };

__shared__ ScanSmem s_scan;
__shared__ Xp0Smem  s_x0;
__shared__ Xp1Smem  s_x1;

// ============================================================
// scan role: 2 batches per 8-CTA cluster; bulk h-exchange;
// per-step gated on xp flags (g_f0 for L0, g_f1 for L1)
// ============================================================
__device__ void scan_role(int layer, int pair, int j,
                          const float* __restrict__ w_hh,
                          const float* __restrict__ thought)
{
  const int tid = threadIdx.x;
  const int u = tid >> 3, kp = tid & 7;
  const int ug = 32*j + u;
  const int B0 = pair*2;

  float wreg[4][32];
  #pragma unroll
  for (int g=0; g<4; g++){
    const float* wp = w_hh + (size_t)(g*256 + ug)*HID + 32*kp;
    #pragma unroll
    for (int q=0;q<8;q++){
      float4 v = *(const float4*)(wp + 4*q);
      wreg[g][4*q+0]=v.x; wreg[g][4*q+1]=v.y; wreg[g][4*q+2]=v.z; wreg[g][4*q+3]=v.w;
    }
  }

  const uint32_t mb0 = smem_u32(&s_scan.mbar[0]);
  const uint32_t mb1 = smem_u32(&s_scan.mbar[1]);
  if (tid == 0) {
    mbar_init_(mb0, 1); mbar_init_(mb1, 1);
    mbar_expect_tx_(mb0, 2048); mbar_expect_tx_(mb1, 2048);
  }
  for (int i = tid; i < 512; i += 256){
    int jj = i >> 6, bb = (i >> 5) & 1, uu = i & 31;
    s_scan.h_s[0][i] = thought[(B0+bb)*HID + jj*32 + uu];
  }
  __syncthreads();
  cluster_sync_();   // peers' mbarriers initialized before any bulk

  const uint32_t hs0 = smem_u32(&s_scan.h_s[0][0]);
  const uint32_t hs1 = smem_u32(&s_scan.h_s[1][0]);
  const uint32_t sg0 = smem_u32(&s_scan.stg[0][0]);
  const uint32_t sg1 = smem_u32(&s_scan.stg[1][0]);

  uint32_t rd0=0, rd1=0, rb0=0, rb1=0;
  if (tid < 8) {
    rd0 = mapa_(hs0 + (uint32_t)j*256u, (uint32_t)tid);
    rd1 = mapa_(hs1 + (uint32_t)j*256u, (uint32_t)tid);
    rb0 = mapa_(mb0, (uint32_t)tid);
    rb1 = mapa_(mb1, (uint32_t)tid);
  }
  const bool owner = (kp == 0);
  float c0 = 0.f, c1 = 0.f;
  uint32_t* fgate = layer ? g_f1 : g_f0;
  float* __restrict__ h_out = layer ? g_h2 : g_h1;

  if (tid == 0) { while (ld_acq_(&fgate[0]) < 32u) { } }
  __syncthreads();
  float4 xv0 = make_float4(0,0,0,0), xv1 = make_float4(0,0,0,0);
  if (owner){
    xv0 = ldcg4_(&g_xp[(size_t)(B0    )*G4 + ug*4]);
    xv1 = ldcg4_(&g_xp[(size_t)(B0 + 1)*G4 + ug*4]);
  }

  for (int t = 0; t < STEPS; t++){
    const int cur = t & 1;
    if (t > 0){
      mbar_wait_(cur ? mb1 : mb0, ((uint32_t)(t-1) >> 1) & 1u);
      if (tid == 0) mbar_expect_tx_(cur ? mb1 : mb0, 2048);
    }

    float a00=0.f,a01=0.f,a02=0.f,a03=0.f, a10=0.f,a11=0.f,a12=0.f,a13=0.f;
    {
      const float4* hA = (const float4*)&s_scan.h_s[cur][kp*64];
      #pragma unroll
      for (int q=0;q<8;q++){
        float4 hv = hA[q];
        a00=fmaf(wreg[0][4*q+0],hv.x,a00); a00=fmaf(wreg[0][4*q+1],hv.y,a00);
        a00=fmaf(wreg[0][4*q+2],hv.z,a00); a00=fmaf(wreg[0][4*q+3],hv.w,a00);
        a01=fmaf(wreg[1][4*q+0],hv.x,a01); a01=fmaf(wreg[1][4*q+1],hv.y,a01);
        a01=fmaf(wreg[1][4*q+2],hv.z,a01); a01=fmaf(wreg[1][4*q+3],hv.w,a01);
        a02=fmaf(wreg[2][4*q+0],hv.x,a02); a02=fmaf(wreg[2][4*q+1],hv.y,a02);
        a02=fmaf(wreg[2][4*q+2],hv.z,a02); a02=fmaf(wreg[2][4*q+3],hv.w,a02);
        a03=fmaf(wreg[3][4*q+0],hv.x,a03); a03=fmaf(wreg[3][4*q+1],hv.y,a03);
        a03=fmaf(wreg[3][4*q+2],hv.z,a03); a03=fmaf(wreg[3][4*q+3],hv.w,a03);
      }
      const float4* hB = (const float4*)&s_scan.h_s[cur][kp*64 + 32];
      #pragma unroll
      for (int q=0;q<8;q++){
        float4 hv = hB[q];
        a10=fmaf(wreg[0][4*q+0],hv.x,a10); a10=fmaf(wreg[0][4*q+1],hv.y,a10);
        a10=fmaf(wreg[0][4*q+2],hv.z,a10); a10=fmaf(wreg[0][4*q+3],hv.w,a10);
        a11=fmaf(wreg[1][4*q+0],hv.x,a11); a11=fmaf(wreg[1][4*q+1],hv.y,a11);
        a11=fmaf(wreg[1][4*q+2],hv.z,a11); a11=fmaf(wreg[1][4*q+3],hv.w,a11);
        a12=fmaf(wreg[2][4*q+0],hv.x,a12); a12=fmaf(wreg[2][4*q+1],hv.y,a12);
        a12=fmaf(wreg[2][4*q+2],hv.z,a12); a12=fmaf(wreg[2][4*q+3],hv.w,a12);
        a13=fmaf(wreg[3][4*q+0],hv.x,a13); a13=fmaf(wreg[3][4*q+1],hv.y,a13);
        a13=fmaf(wreg[3][4*q+2],hv.z,a13); a13=fmaf(wreg[3][4*q+3],hv.w,a13);
      }
    }
    #pragma unroll
    for (int off=4; off>=1; off>>=1) {
      a00 += __shfl_xor_sync(0xffffffffu, a00, off);
      a01 += __shfl_xor_sync(0xffffffffu, a01, off);
      a02 += __shfl_xor_sync(0xffffffffu, a02, off);
      a03 += __shfl_xor_sync(0xffffffffu, a03, off);
      a10 += __shfl_xor_sync(0xffffffffu, a10, off);
      a11 += __shfl_xor_sync(0xffffffffu, a11, off);
      a12 += __shfl_xor_sync(0xffffffffu, a12, off);
      a13 += __shfl_xor_sync(0xffffffffu, a13, off);
    }

    // gate next step's xp availability (before the CTA-wide bar)
    if (tid == 0 && t + 1 < STEPS) {
      while (ld_acq_(&fgate[t+1]) < 32u) { }
    }

    if (owner) {
      float gi = sigmoidf_(a00 + xv0.x);
      float gf = sigmoidf_(a01 + xv0.y);
      float gg = 2.f*sigmoidf_(2.f*(a02 + xv0.z)) - 1.f;
      float go = sigmoidf_(a03 + xv0.w);
      c0 = gf*c0 + gi*gg;
      float h0 = go * (2.f*sigmoidf_(2.f*c0) - 1.f);
      gi = sigmoidf_(a10 + xv1.x);
      gf = sigmoidf_(a11 + xv1.y);
      gg = 2.f*sigmoidf_(2.f*(a12 + xv1.z)) - 1.f;
      go = sigmoidf_(a13 + xv1.w);
      c1 = gf*c1 + gi*gg;
      float h1 = go * (2.f*sigmoidf_(2.f*c1) - 1.f);
      s_scan.stg[cur^1][u]      = h0;
      s_scan.stg[cur^1][32 + u] = h1;
    }
    __syncthreads();

    if (t + 1 < STEPS && tid < 8) {
      fence_proxy_async_();
      bulk_s2c_(cur ? rd0 : rd1, cur ? sg0 : sg1, 256u, cur ? rb0 : rb1);
    }
    // publish h rows to gmem (both layers); L0 additionally counts fh
    if (tid < 16) {
      int bb = tid >> 3, q = tid & 7;
      float4 hv4 = *(const float4*)&s_scan.stg[cur^1][bb*32 + 4*q];
      *(float4*)&h_out[(size_t)(t*BATCH + B0 + bb)*HID + 32*j + 4*q] = hv4;
      if (layer == 0) red_rel_add_(&g_fh[t]);    // 16 per CTA, 32 CTAs -> 512
    }
    if (owner && t + 1 < STEPS) {
      xv0 = ldcg4_(&g_xp[(size_t)((t+1)*BATCH + B0    )*G4 + ug*4]);
      xv1 = ldcg4_(&g_xp[(size_t)((t+1)*BATCH + B0 + 1)*G4 + ug*4]);
    }
  }
}

// ============================================================
// xp0 streamer role: 32 CTAs, CTA idx owns g_xp cols [32*idx, 32*idx+32)
// free-running over t; then converts out_w (wcat) in its idle tail
// ============================================================
__device__ void xp0_role(int idx,
                         const int* __restrict__ captions,
                         const float* __restrict__ emb_w,
                         const float* __restrict__ W,
                         const float* __restrict__ b1,
                         const float* __restrict__ b2,
                         const float* __restrict__ ow)
{
  const int tid = threadIdx.x;
  const int ccl = tid >> 3, kp = tid & 7;
  const int cc = idx*32 + ccl;
  const int wrow = (cc & 3)*256 + (cc >> 2);   // gate*256 + unit

  float wreg[16];
  #pragma unroll
  for (int q=0;q<4;q++){
    float4 v = *(const float4*)&W[(size_t)wrow*128 + kp*16 + 4*q];
    wreg[4*q+0]=v.x; wreg[4*q+1]=v.y; wreg[4*q+2]=v.z; wreg[4*q+3]=v.w;
  }
  const float bv = b1[wrow] + b2[wrow];

  for (int t = 0; t < STEPS; t++){
    if (tid < 8) s_x0.cap[tid] = captions[tid*512 + t];
    __syncthreads();
    {
      int i = tid*4; int row = i >> 7, k = i & 127;
      *(float4*)&s_x0.Hs[row][k] = *(const float4*)&emb_w[(size_t)s_x0.cap[row]*128 + k];
    }
    __syncthreads();

    float out[8];
    #pragma unroll
    for (int r=0;r<8;r++){
      float acc = 0.f;
      #pragma unroll
      for (int q=0;q<4;q++){
        float4 hv = *(const float4*)&s_x0.Hs[r][kp*16 + 4*q];
        acc = fmaf(wreg[4*q+0],hv.x,acc); acc = fmaf(wreg[4*q+1],hv.y,acc);
        acc = fmaf(wreg[4*q+2],hv.z,acc); acc = fmaf(wreg[4*q+3],hv.w,acc);
      }
      #pragma unroll
      for (int off=4; off>=1; off>>=1)
        acc += __shfl_xor_sync(0xffffffffu, acc, off);
      out[r] = acc;
    }
    if (kp == 0){
      #pragma unroll
      for (int r=0;r<8;r++)
        g_xp[(size_t)(t*BATCH + r)*G4 + cc] = out[r] + bv;
    }
    __syncthreads();
    if (tid == 0) red_rel_add_(&g_f0[t]);
  }

  // idle tail: out_w split-bf16 conversion (wcat), vocab strided by 32 CTAs
  for (int v = idx; v < VOCAB; v += 32){
    float w = ow[(size_t)v*HID + tid];
    __nv_bfloat16 hi = __float2bfloat16(w);
    __nv_bfloat16 lo = __float2bfloat16(w - __bfloat162float(hi));
    __nv_bfloat16* row = g_wcat + (size_t)v*KCAT;
    row[tid] = hi; row[HID + tid] = hi; row[2*HID + tid] = lo;
  }
}

// ============================================================
// xp1 streamer role: 32 CTAs, CTA idx owns g_xp cols [32*idx, +32);
// gated per-t on g_fh (h1 published), publishes g_f1
// ============================================================
__device__ void xp1_role(int idx,
                         const float* __restrict__ W,
                         const float* __restrict__ b1,
                         const float* __restrict__ b2)
{
  const int tid = threadIdx.x;
  const int ccl = tid >> 3, kp = tid & 7;
  const int cc = idx*32 + ccl;
  const int wrow = (cc & 3)*256 + (cc >> 2);

  float wreg[32];
  #pragma unroll
  for (int q=0;q<8;q++){
    float4 v = *(const float4*)&W[(size_t)wrow*HID + kp*32 + 4*q];
    wreg[4*q+0]=v.x; wreg[4*q+1]=v.y; wreg[4*q+2]=v.z; wreg[4*q+3]=v.w;
  }
  const float bv = b1[wrow] + b2[wrow];

  for (int t = 0; t < STEPS; t++){
    if (tid == 0){ while (ld_acq_(&g_fh[t]) < 512u) { } }
    __syncthreads();
    {
      int row = tid >> 5, k = (tid & 31)*8;
      *(float4*)&s_x1.Hs[row][k]   = ldcg4_(&g_h1[(size_t)(t*BATCH + row)*HID + k]);
      *(float4*)&s_x1.Hs[row][k+4] = ldcg4_(&g_h1[(size_t)(t*BATCH + row)*HID + k + 4]);
    }
    __syncthreads();

    float out[8];
    #pragma unroll
    for (int r=0;r<8;r++){
      float acc = 0.f;
      #pragma unroll
      for (int q=0;q<8;q++){
        float4 hv = *(const float4*)&s_x1.Hs[r][kp*32 + 4*q];
        acc = fmaf(wreg[4*q+0],hv.x,acc); acc = fmaf(wreg[4*q+1],hv.y,acc);
        acc = fmaf(wreg[4*q+2],hv.z,acc); acc = fmaf(wreg[4*q+3],hv.w,acc);
      }
      #pragma unroll
      for (int off=4; off>=1; off>>=1)
        acc += __shfl_xor_sync(0xffffffffu, acc, off);
      out[r] = acc;
    }
    if (kp == 0){
      #pragma unroll
      for (int r=0;r<8;r++)
        g_xp[(size_t)(t*BATCH + r)*G4 + cc] = out[r] + bv;
    }
    __syncthreads();
    if (tid == 0) red_rel_add_(&g_f1[t]);
  }
}

// ============================================================
// fused pipeline: 128 CTAs = 16 clusters of 8, all wave-1 resident
// ============================================================
__global__ void __launch_bounds__(256,1) __cluster_dims__(8,1,1)
pipe_kernel(const float* __restrict__ w_hh0, const float* __restrict__ w_hh1,
            const float* __restrict__ thought,
            const int* __restrict__ captions, const float* __restrict__ emb_w,
            const float* __restrict__ w_ih0, const float* __restrict__ bih0, const float* __restrict__ bhh0,
            const float* __restrict__ w_ih1, const float* __restrict__ bih1, const float* __restrict__ bhh1,
            const float* __restrict__ ow)
{
  const int bid = blockIdx.x;
  const int cid = bid >> 3;
  if (cid < 4)       scan_role(0, cid,     bid & 7, w_hh0, thought);
  else if (cid < 8)  scan_role(1, cid - 4, bid & 7, w_hh1, thought);
  else if (cid < 12) xp0_role(bid - 64, captions, emb_w, w_ih0, bih0, bhh0, ow);
  else               xp1_role(bid - 96, w_ih1, bih1, bhh1);
}

// ============================================================
// gate MLP fused with gated-h2 split-bf16 conversion (acat)
// ============================================================
__global__ void __launch_bounds__(256) gateacat_kernel(
    const float* __restrict__ gw1, const float* __restrict__ gb1,
    const float* __restrict__ gw2, const float* __restrict__ gb2)
{
  __shared__ __align__(16) float Hs[8][256];
  __shared__ float wp_s[8][8];
  __shared__ float gatev[8];
  const int tid = threadIdx.x;
  const int r0  = blockIdx.x * 8;

  if (r0 >= NROWS) {   // padding rows: zero fill
    __nv_bfloat16 z = __float2bfloat16(0.f);
    #pragma unroll
    for (int row=0; row<8; row++){
      __nv_bfloat16* rp = g_acat + (size_t)(r0+row)*KCAT;
      rp[tid] = z; rp[HID+tid] = z; rp[2*HID+tid] = z;
    }
    return;
  }

  for (int idx = tid; idx < 8*256; idx += 256) {
    int row = idx >> 8, k = idx & 255;
    Hs[row][k] = g_h2[(size_t)(r0+row)*HID + k];
  }
  __syncthreads();

  float u[8];
  #pragma unroll
  for (int r=0;r<8;r++) u[r]=0.f;
  const float* wrow = gw1 + (size_t)tid*256;
  #pragma unroll 8
  for (int k0=0;k0<256;k0+=4){
    float4 w4 = *(const float4*)(wrow + k0);
    #pragma unroll
    for (int r=0;r<8;r++) {
      float4 a4 = *(const float4*)&Hs[r][k0];
      u[r] = fmaf(w4.x, a4.x, u[r]); u[r] = fmaf(w4.y, a4.y, u[r]);
      u[r] = fmaf(w4.z, a4.z, u[r]); u[r] = fmaf(w4.w, a4.w, u[r]);
    }
  }
  float g2 = gw2[tid], b1v = gb1[tid];
  float p[8];
  #pragma unroll
  for (int r=0;r<8;r++) p[r] = tanhf(u[r] + b1v) * g2;
  #pragma unroll
  for (int off=16; off>=1; off>>=1)
    #pragma unroll
    for (int r=0;r<8;r++) p[r] += __shfl_xor_sync(0xffffffffu, p[r], off);
  if ((tid & 31) == 0)
    #pragma unroll
    for (int r=0;r<8;r++) wp_s[tid>>5][r] = p[r];
  __syncthreads();
  if (tid < 8) {
    float s = 0.f;
    #pragma unroll
    for (int w=0;w<8;w++) s += wp_s[w][tid];
    gatev[tid] = sigmoidf_(s + gb2[0]);
  }
  __syncthreads();

  #pragma unroll
  for (int row=0; row<8; row++){
    float a = Hs[row][tid] * gatev[row];
    __nv_bfloat16 hi = __float2bfloat16(a);
    __nv_bfloat16 lo = __float2bfloat16(a - __bfloat162float(hi));
    __nv_bfloat16* rp = g_acat + (size_t)(r0+row)*KCAT;
    rp[tid] = hi; rp[HID+tid] = lo; rp[2*HID+tid] = hi;
  }
}

// ============================================================
// vocab GEMM: mma.sync bf16 split-concat K=768
// ============================================================
#define KC 64
#define NCHUNK (KCAT/KC)             // 12
#define STAGE_HALF 16384
#define STAGE_SZ   32768
#define EPS_STRIDE 132
#define GSMEM (2*STAGE_SZ + 4096)

__global__ void __launch_bounds__(256) out_gemm_mma(
    const float* __restrict__ ob, float* __restrict__ outp)
{
  extern __shared__ __align__(128) char smg[];
  const uint32_t sbase = smem_u32(smg);
  float* eps = (float*)smg;
  const int tid  = threadIdx.x;
  const int wid  = tid >> 5;
  const int lane = tid & 31;
  const int bn = blockIdx.x * 128;
  const int bm = blockIdx.y * 128;
  const int wm = (wid & 1) * 64;
  const int wn = (wid >> 1) * 32;

  const int lrow = tid >> 1;
  const int lseg4 = (tid & 1) * 4;
  #pragma unroll
  for (int c = 0; c < 2; c++) {
    const uint32_t st = sbase + c*STAGE_SZ;
    const char* wg = (const char*)g_wcat + ((size_t)(bm+lrow)*KCAT + c*KC)*2;
    const char* ag = (const char*)g_acat + ((size_t)(bn+lrow)*KCAT + c*KC)*2;
    #pragma unroll
    for (int q=0;q<4;q++){
      uint32_t off = sw128_((uint32_t)(lrow*128 + (lseg4+q)*16));
      cp_async16_(st + off, wg + (lseg4+q)*16);
      cp_async16_(st + STAGE_HALF + off, ag + (lseg4+q)*16);
    }
    CP_COMMIT();
  }
  float acc[4][4][4];
  #pragma unroll
  for (int i=0;i<4;i++)
    #pragma unroll
    for (int jj=0;jj<4;jj++)
      #pragma unroll
      for (int v=0;v<4;v++) acc[i][jj][v]=0.f;
  const uint32_t a_row = (uint32_t)(lane & 15);
  const uint32_t a_k16 = (uint32_t)((lane >> 4) * 16);
  const uint32_t b_row = (uint32_t)((lane & 7) + ((lane & 16) >> 1));
  const uint32_t b_k16 = (uint32_t)((lane & 8) ? 16 : 0);
  for (int c = 0; c < NCHUNK; c++) {
    CP_WAIT1();
    __syncthreads();
    const uint32_t wbase = sbase + (c & 1)*STAGE_SZ;
    const uint32_t abase = wbase + STAGE_HALF;
    #pragma unroll
    for (int k = 0; k < 4; k++) {
      uint32_t af[4][4], bf[2][4];
      #pragma unroll
      for (int mt=0; mt<4; mt++)
        ldsm_x4_(af[mt], wbase + sw128_((uint32_t)((wm + mt*16 + a_row)*128) + k*32 + a_k16));
      #pragma unroll
      for (int nt2=0; nt2<2; nt2++)
        ldsm_x4_(bf[nt2], abase + sw128_((uint32_t)((wn + nt2*16 + b_row)*128) + k*32 + b_k16));
      #pragma unroll
      for (int mt=0; mt<4; mt++)
        #pragma unroll
        for (int nt=0; nt<4; nt++)
          mma16816_(acc[mt][nt], af[mt], &bf[nt>>1][(nt&1)*2]);
    }
    __syncthreads();
    if (c + 2 < NCHUNK) {
      const uint32_t st = sbase + (c & 1)*STAGE_SZ;
      const char* wg = (const char*)g_wcat + ((size_t)(bm+lrow)*KCAT + (c+2)*KC)*2;
      const char* ag = (const char*)g_acat + ((size_t)(bn+lrow)*KCAT + (c+2)*KC)*2;
      #pragma unroll
      for (int q=0;q<4;q++){
        uint32_t off = sw128_((uint32_t)(lrow*128 + (lseg4+q)*16));
        cp_async16_(st + off, wg + (lseg4+q)*16);
        cp_async16_(st + STAGE_HALF + off, ag + (lseg4+q)*16);
      }
    }
    CP_COMMIT();
  }
  CP_WAIT0();
  {
    const int mq = lane >> 2;
    const int nq = (lane & 3) * 2;
    #pragma unroll
    for (int mt=0; mt<4; mt++)
      #pragma unroll
      for (int nt=0; nt<4; nt++){
        int m0 = wm + mt*16 + mq;
        int n0 = wn + nt*8 + nq;
        eps[(n0  )*EPS_STRIDE + m0    ] = acc[mt][nt][0];
        eps[(n0+1)*EPS_STRIDE + m0    ] = acc[mt][nt][1];
        eps[(n0  )*EPS_STRIDE + m0 + 8] = acc[mt][nt][2];
        eps[(n0+1)*EPS_STRIDE + m0 + 8] = acc[mt][nt][3];
      }
  }
  __syncthreads();
  {
    const int mo = (tid & 15) * 8;
    const int vg = bm + mo;
    float4 ob0 = *(const float4*)&ob[vg];
    float4 ob1 = *(const float4*)&ob[vg+4];
    #pragma unroll
    for (int it = 0; it < 8; it++) {
      int n = (tid >> 4) + it*16;
      int r = bn + n;
      if (r < NROWS) {
        const float* ep = eps + n*EPS_STRIDE + mo;
        float4 v0 = *(const float4*)ep;
        float4 v1 = *(const float4*)(ep+4);
        v0.x+=ob0.x; v0.y+=ob0.y; v0.z+=ob0.z; v0.w+=ob0.w;
        v1.x+=ob1.x; v1.y+=ob1.y; v1.z+=ob1.z; v1.w+=ob1.w;
        float* op = outp + (size_t)((r & 7)*STEPS + (r >> 3))*VOCAB + vg;
        *(float4*)op     = v0;
        *(float4*)(op+4) = v1;
      }
    }
  }
}

// ============================================================
extern "C" void kernel_launch(void* const* d_in, const int* in_sizes, int n_in,
                              void* d_out, int out_size) {
  const float* thought = (const float*)d_in[0];
  const int*   captions= (const int*)  d_in[1];
  const float* emb_w   = (const float*)d_in[2];
  const float* w_ih0   = (const float*)d_in[3];
  const float* w_hh0   = (const float*)d_in[4];
  const float* b_ih0   = (const float*)d_in[5];
  const float* b_hh0   = (const float*)d_in[6];
  const float* w_ih1   = (const float*)d_in[7];
  const float* w_hh1   = (const float*)d_in[8];
  const float* b_ih1   = (const float*)d_in[9];
  const float* b_hh1   = (const float*)d_in[10];
  const float* gw1     = (const float*)d_in[11];
  const float* gb1     = (const float*)d_in[12];
  const float* gw2     = (const float*)d_in[13];
  const float* gb2     = (const float*)d_in[14];
  const float* ow      = (const float*)d_in[15];
  const float* ob      = (const float*)d_in[16];
  float* outp = (float*)d_out;

  cudaFuncSetAttribute(out_gemm_mma, cudaFuncAttributeMaxDynamicSharedMemorySize, GSMEM);

  // single-stream chain; all cross-stage overlap happens INSIDE pipe_kernel
  clearflags_kernel<<<4, 256>>>();
  pipe_kernel<<<128, 256>>>(w_hh0, w_hh1, thought, captions, emb_w,
                            w_ih0, b_ih0, b_hh0, w_ih1, b_ih1, b_hh1, ow);
  gateacat_kernel<<<512, 256>>>(gw1, gb1, gw2, gb2);
  dim3 gg(NPAD/128, VOCAB/128);   // (32, 250)
  out_gemm_mma<<<gg, 256, GSMEM>>>(ob, outp);
}

// round 10
// speedup vs baseline: 2.7003x; 2.7003x over previous
#include <cuda_runtime.h>
#include <cuda_bf16.h>
#include <cstdint>
#include <math.h>

#define STEPS 511
#define BATCH 8
#define HID   256
#define G4    1024
#define VOCAB 32000
#define NROWS (STEPS*BATCH)   // 4088
#define NPAD  4096
#define KCAT  768             // [hi | hi/lo split] concat K

// ---------------- scratch (no allocs allowed) ----------------
__device__ float g_xp[STEPS*BATCH*G4];                // gate-interleaved: [r][unit*4+gate]
__device__ float g_h1[STEPS*BATCH*HID];
__device__ float g_h2[STEPS*BATCH*HID];
__device__ __nv_bfloat16 g_wcat[(size_t)VOCAB*KCAT];  // 49 MB  out_w split
__device__ __nv_bfloat16 g_acat[(size_t)NPAD*KCAT];   // 6.3 MB (h1-split, then gated-h2-split)
__device__ __nv_bfloat16 g_xw[(size_t)G4*KCAT];       // 1.5 MB  w_ih1 split

__device__ __forceinline__ float sigmoidf_(float x){ return 1.0f/(1.0f + __expf(-x)); }

__device__ __forceinline__ uint32_t smem_u32(const void* p){
  return (uint32_t)__cvta_generic_to_shared(p);
}
__device__ __forceinline__ void mbar_init_(uint32_t a, uint32_t cnt){
  asm volatile("mbarrier.init.shared.b64 [%0], %1;" :: "r"(a), "r"(cnt) : "memory");
}
__device__ __forceinline__ void mbar_expect_tx_(uint32_t a, uint32_t bytes){
  asm volatile("mbarrier.arrive.expect_tx.shared.b64 _, [%0], %1;" :: "r"(a), "r"(bytes) : "memory");
}
__device__ __forceinline__ void mbar_wait_(uint32_t a, uint32_t phase){
  asm volatile("{\n\t.reg .pred P;\n\t"
    "WL_%=:\n\t"
    "mbarrier.try_wait.parity.acquire.cta.shared::cta.b64 P, [%0], %1, 0x989680;\n\t"
    "@P bra.uni WD_%=;\n\t"
    "bra.uni WL_%=;\n\t"
    "WD_%=:\n\t}" :: "r"(a), "r"(phase) : "memory");
}
__device__ __forceinline__ void st_async_b32_(uint32_t saddr, uint32_t smbar, uint32_t rank, uint32_t v){
  asm volatile("{\n\t.reg .b32 ra, rb;\n\t"
    "mapa.shared::cluster.u32 ra, %0, %2;\n\t"
    "mapa.shared::cluster.u32 rb, %1, %2;\n\t"
    "st.async.shared::cluster.mbarrier::complete_tx::bytes.b32 [ra], %3, [rb];\n\t}"
    :: "r"(saddr), "r"(smbar), "r"(rank), "r"(v) : "memory");
}
__device__ __forceinline__ void cluster_sync_(){
  asm volatile("barrier.cluster.arrive.aligned;" ::: "memory");
  asm volatile("barrier.cluster.wait.aligned;"   ::: "memory");
}
__device__ __forceinline__ void cp_async16_(uint32_t saddr, const void* gaddr){
  asm volatile("cp.async.cg.shared.global [%0], [%1], 16;" :: "r"(saddr), "l"(gaddr) : "memory");
}
#define CP_COMMIT() asm volatile("cp.async.commit_group;" ::: "memory")
#define CP_WAIT1()  asm volatile("cp.async.wait_group 1;" ::: "memory")
#define CP_WAIT0()  asm volatile("cp.async.wait_group 0;" ::: "memory")

__device__ __forceinline__ void ldsm_x4_(uint32_t* r, uint32_t addr){
  asm volatile("ldmatrix.sync.aligned.m8n8.x4.shared.b16 {%0,%1,%2,%3}, [%4];"
    : "=r"(r[0]), "=r"(r[1]), "=r"(r[2]), "=r"(r[3]) : "r"(addr));
}
__device__ __forceinline__ void mma16816_(float* d, const uint32_t* a, const uint32_t* b){
  asm volatile("mma.sync.aligned.m16n8k16.row.col.f32.bf16.bf16.f32 "
    "{%0,%1,%2,%3}, {%4,%5,%6,%7}, {%8,%9}, {%0,%1,%2,%3};"
    : "+f"(d[0]), "+f"(d[1]), "+f"(d[2]), "+f"(d[3])
    : "r"(a[0]), "r"(a[1]), "r"(a[2]), "r"(a[3]), "r"(b[0]), "r"(b[1]));
}
static __device__ __forceinline__ uint32_t sw128_(uint32_t b){ return b ^ ((b >> 3) & 0x70u); }

// ============================================================
// Layer-0 input projection (K=128), gate-interleaved output (R5 exact)
// ============================================================
__global__ void __launch_bounds__(256) xp0_kernel(
    const int* __restrict__ captions, const float* __restrict__ emb_w,
    const float* __restrict__ W, const float* __restrict__ bias1,
    const float* __restrict__ bias2)
{
  __shared__ __align__(16) float As[8][128];
  const int tid = threadIdx.x;
  const int r0  = blockIdx.x * 8;

  for (int idx = tid; idx < 8*128; idx += 256) {
    int row = idx >> 7, k = idx & 127;
    int r = r0 + row;
    int b = r & 7, t = r >> 3;
    As[row][k] = emb_w[(size_t)captions[b*512 + t] * 128 + k];
  }
  __syncthreads();

  float acc[4][8];
  #pragma unroll
  for (int i=0;i<4;i++)
    #pragma unroll
    for (int r=0;r<8;r++) acc[i][r]=0.f;

  const int c0 = tid;   // unit
  for (int k0 = 0; k0 < 128; k0 += 4) {
    float4 w0 = *(const float4*)&W[(size_t)(c0      )*128 + k0];
    float4 w1 = *(const float4*)&W[(size_t)(c0+256)*128 + k0];
    float4 w2 = *(const float4*)&W[(size_t)(c0+512)*128 + k0];
    float4 w3 = *(const float4*)&W[(size_t)(c0+768)*128 + k0];
    #pragma unroll
    for (int r=0;r<8;r++) {
      float4 a4 = *(const float4*)&As[r][k0];
      acc[0][r] = fmaf(w0.x, a4.x, acc[0][r]); acc[0][r] = fmaf(w0.y, a4.y, acc[0][r]);
      acc[0][r] = fmaf(w0.z, a4.z, acc[0][r]); acc[0][r] = fmaf(w0.w, a4.w, acc[0][r]);
      acc[1][r] = fmaf(w1.x, a4.x, acc[1][r]); acc[1][r] = fmaf(w1.y, a4.y, acc[1][r]);
      acc[1][r] = fmaf(w1.z, a4.z, acc[1][r]); acc[1][r] = fmaf(w1.w, a4.w, acc[1][r]);
      acc[2][r] = fmaf(w2.x, a4.x, acc[2][r]); acc[2][r] = fmaf(w2.y, a4.y, acc[2][r]);
      acc[2][r] = fmaf(w2.z, a4.z, acc[2][r]); acc[2][r] = fmaf(w2.w, a4.w, acc[2][r]);
      acc[3][r] = fmaf(w3.x, a4.x, acc[3][r]); acc[3][r] = fmaf(w3.y, a4.y, acc[3][r]);
      acc[3][r] = fmaf(w3.z, a4.z, acc[3][r]); acc[3][r] = fmaf(w3.w, a4.w, acc[3][r]);
    }
  }
  float bb[4];
  #pragma unroll
  for (int i=0;i<4;i++) bb[i] = bias1[c0+i*256] + bias2[c0+i*256];
  #pragma unroll
  for (int r=0;r<8;r++) {
    float4 o;
    o.x = acc[0][r]+bb[0]; o.y = acc[1][r]+bb[1];
    o.z = acc[2][r]+bb[2]; o.w = acc[3][r]+bb[3];
    *(float4*)&g_xp[(size_t)(r0+r)*G4 + c0*4] = o;
  }
}

// ============================================================
// LSTM scan (R5's lstm_scan2, + xpv prefetch hoisted before wait)
// ============================================================
__global__ __launch_bounds__(256,1) __cluster_dims__(8,1,1)
void lstm_scan2(const float* __restrict__ w_hh,
                const float* __restrict__ thought,
                int layer)
{
  __shared__ __align__(16) float h_s[2][HID];
  __shared__ __align__(8) unsigned long long mbar_sto[2];

  float* __restrict__ h_out = layer ? g_h2 : g_h1;

  const int tid = threadIdx.x;
  const int b   = blockIdx.x >> 3;
  const int j   = blockIdx.x & 7;
  const int u   = tid >> 3;
  const int kp  = tid & 7;
  const int ug  = 32*j + u;

  float wreg[4][32];
  #pragma unroll
  for (int g=0; g<4; g++){
    const float* wp = w_hh + (size_t)(g*256 + ug)*HID + 32*kp;
    #pragma unroll
    for (int q=0;q<8;q++){
      float4 v = *(const float4*)(wp + 4*q);
      wreg[g][4*q+0]=v.x; wreg[g][4*q+1]=v.y; wreg[g][4*q+2]=v.z; wreg[g][4*q+3]=v.w;
    }
  }

  const uint32_t mb0 = smem_u32(&mbar_sto[0]);
  const uint32_t mb1 = smem_u32(&mbar_sto[1]);
  if (tid == 0) {
    mbar_init_(mb0, 1); mbar_init_(mb1, 1);
    mbar_expect_tx_(mb0, 1024); mbar_expect_tx_(mb1, 1024);
  }
  h_s[0][tid] = thought[b*HID + tid];
  __syncthreads();
  cluster_sync_();

  const uint32_t hs0 = smem_u32(&h_s[0][0]);
  const uint32_t hs1 = smem_u32(&h_s[1][0]);
  const bool owner = (kp == 0);
  float c = 0.f;

  for (int t = 0; t < STEPS; t++) {
    const int cur = t & 1;

    // prefetch xp before the wait (independent of h-exchange)
    float4 xpv = make_float4(0.f,0.f,0.f,0.f);
    if (owner)
      xpv = *(const float4*)&g_xp[(size_t)(t*BATCH + b)*G4 + ug*4];

    if (t > 0) {
      mbar_wait_(cur ? mb1 : mb0, ((uint32_t)(t-1) >> 1) & 1u);
      if (tid == 0) mbar_expect_tx_(cur ? mb1 : mb0, 1024);
    }

    float a0=0.f,a1=0.f,a2=0.f,a3=0.f;
    const float4* h4 = (const float4*)&h_s[cur][32*kp];
    #pragma unroll
    for (int q=0;q<8;q++) {
      float4 hv = h4[q];
      a0=fmaf(wreg[0][4*q+0],hv.x,a0); a0=fmaf(wreg[0][4*q+1],hv.y,a0);
      a0=fmaf(wreg[0][4*q+2],hv.z,a0); a0=fmaf(wreg[0][4*q+3],hv.w,a0);
      a1=fmaf(wreg[1][4*q+0],hv.x,a1); a1=fmaf(wreg[1][4*q+1],hv.y,a1);
      a1=fmaf(wreg[1][4*q+2],hv.z,a1); a1=fmaf(wreg[1][4*q+3],hv.w,a1);
      a2=fmaf(wreg[2][4*q+0],hv.x,a2); a2=fmaf(wreg[2][4*q+1],hv.y,a2);
      a2=fmaf(wreg[2][4*q+2],hv.z,a2); a2=fmaf(wreg[2][4*q+3],hv.w,a2);
      a3=fmaf(wreg[3][4*q+0],hv.x,a3); a3=fmaf(wreg[3][4*q+1],hv.y,a3);
      a3=fmaf(wreg[3][4*q+2],hv.z,a3); a3=fmaf(wreg[3][4*q+3],hv.w,a3);
    }
    #pragma unroll
    for (int off=4; off>=1; off>>=1) {
      a0 += __shfl_xor_sync(0xffffffffu, a0, off);
      a1 += __shfl_xor_sync(0xffffffffu, a1, off);
      a2 += __shfl_xor_sync(0xffffffffu, a2, off);
      a3 += __shfl_xor_sync(0xffffffffu, a3, off);
    }

    if (owner) {
      float gi = sigmoidf_(a0 + xpv.x);
      float gf = sigmoidf_(a1 + xpv.y);
      float gg = 2.f*sigmoidf_(2.f*(a2 + xpv.z)) - 1.f;   // tanh
      float go = sigmoidf_(a3 + xpv.w);
      c = gf*c + gi*gg;
      float h = go * (2.f*sigmoidf_(2.f*c) - 1.f);
      h_out[(size_t)(t*BATCH+b)*HID + ug] = h;
      if (t + 1 < STEPS) {
        uint32_t daddr = (cur ? hs0 : hs1) + (uint32_t)ug*4u;
        uint32_t dmb   = cur ? mb0 : mb1;
        uint32_t hv = __float_as_uint(h);
        #pragma unroll
        for (int p=0;p<8;p++) st_async_b32_(daddr, dmb, (uint32_t)p, hv);
      }
    }
  }
}

// ============================================================
// gate MLP fused with gated-h2 split-bf16 conversion (R6-proven)
// ============================================================
__global__ void __launch_bounds__(256) gateacat_kernel(
    const float* __restrict__ gw1, const float* __restrict__ gb1,
    const float* __restrict__ gw2, const float* __restrict__ gb2)
{
  __shared__ __align__(16) float Hs[8][256];
  __shared__ float wp_s[8][8];
  __shared__ float gatev[8];
  const int tid = threadIdx.x;
  const int r0  = blockIdx.x * 8;

  if (r0 >= NROWS) {   // padding rows: zero fill
    __nv_bfloat16 z = __float2bfloat16(0.f);
    #pragma unroll
    for (int row=0; row<8; row++){
      __nv_bfloat16* rp = g_acat + (size_t)(r0+row)*KCAT;
      rp[tid] = z; rp[HID+tid] = z; rp[2*HID+tid] = z;
    }
    return;
  }

  for (int idx = tid; idx < 8*256; idx += 256) {
    int row = idx >> 8, k = idx & 255;
    Hs[row][k] = g_h2[(size_t)(r0+row)*HID + k];
  }
  __syncthreads();

  float u[8];
  #pragma unroll
  for (int r=0;r<8;r++) u[r]=0.f;
  const float* wrow = gw1 + (size_t)tid*256;
  #pragma unroll 8
  for (int k0=0;k0<256;k0+=4){
    float4 w4 = *(const float4*)(wrow + k0);
    #pragma unroll
    for (int r=0;r<8;r++) {
      float4 a4 = *(const float4*)&Hs[r][k0];
      u[r] = fmaf(w4.x, a4.x, u[r]); u[r] = fmaf(w4.y, a4.y, u[r]);
      u[r] = fmaf(w4.z, a4.z, u[r]); u[r] = fmaf(w4.w, a4.w, u[r]);
    }
  }
  float g2 = gw2[tid], b1v = gb1[tid];
  float p[8];
  #pragma unroll
  for (int r=0;r<8;r++) p[r] = tanhf(u[r] + b1v) * g2;
  #pragma unroll
  for (int off=16; off>=1; off>>=1)
    #pragma unroll
    for (int r=0;r<8;r++) p[r] += __shfl_xor_sync(0xffffffffu, p[r], off);
  if ((tid & 31) == 0)
    #pragma unroll
    for (int r=0;r<8;r++) wp_s[tid>>5][r] = p[r];
  __syncthreads();
  if (tid < 8) {
    float s = 0.f;
    #pragma unroll
    for (int w=0;w<8;w++) s += wp_s[w][tid];
    gatev[tid] = sigmoidf_(s + gb2[0]);
  }
  __syncthreads();

  #pragma unroll
  for (int row=0; row<8; row++){
    float a = Hs[row][tid] * gatev[row];
    __nv_bfloat16 hi = __float2bfloat16(a);
    __nv_bfloat16 lo = __float2bfloat16(a - __bfloat162float(hi));
    __nv_bfloat16* rp = g_acat + (size_t)(r0+row)*KCAT;
    rp[tid] = hi; rp[HID+tid] = lo; rp[2*HID+tid] = hi;
  }
}

// ============================================================
// split-bf16 conversion kernels (R5 exact)
// ============================================================
__global__ void __launch_bounds__(256) wcat_kernel(const float* __restrict__ ow){
  const int v = blockIdx.x, k = threadIdx.x;
  float w = ow[(size_t)v*HID + k];
  __nv_bfloat16 hi = __float2bfloat16(w);
  __nv_bfloat16 lo = __float2bfloat16(w - __bfloat162float(hi));
  __nv_bfloat16* row = g_wcat + (size_t)v*KCAT;
  row[k] = hi; row[HID + k] = hi; row[2*HID + k] = lo;
}

__global__ void __launch_bounds__(256) wihcvt_kernel(const float* __restrict__ wih){
  const int m = blockIdx.x, k = threadIdx.x;
  float w = wih[(size_t)m*HID + k];
  __nv_bfloat16 hi = __float2bfloat16(w);
  __nv_bfloat16 lo = __float2bfloat16(w - __bfloat162float(hi));
  __nv_bfloat16* row = g_xw + (size_t)m*KCAT;
  row[k] = hi; row[HID + k] = hi; row[2*HID + k] = lo;
}

__global__ void __launch_bounds__(256) h1cvt_kernel(){
  const int r = blockIdx.x, k = threadIdx.x;
  __nv_bfloat16* row = g_acat + (size_t)r*KCAT;
  if (r < NROWS) {
    float a = g_h1[(size_t)r*HID + k];
    __nv_bfloat16 hi = __float2bfloat16(a);
    __nv_bfloat16 lo = __float2bfloat16(a - __bfloat162float(hi));
    row[k] = hi; row[HID + k] = lo; row[2*HID + k] = hi;
  } else {
    __nv_bfloat16 z = __float2bfloat16(0.f);
    row[k] = z; row[HID + k] = z; row[2*HID + k] = z;
  }
}

// ============================================================
// shared mma mainloop (R5 exact, 2-stage)
// ============================================================
#define KC 64
#define NCHUNK (KCAT/KC)             // 12
#define STAGE_HALF 16384
#define STAGE_SZ   32768
#define EPS_STRIDE 132
#define GSMEM (2*STAGE_SZ + 4096)

#define MMA_MAINLOOP(WSRC, ASRC)                                                  \
  const int lrow = tid >> 1;                                                      \
  const int lseg4 = (tid & 1) * 4;                                                \
  _Pragma("unroll")                                                               \
  for (int c = 0; c < 2; c++) {                                                   \
    const uint32_t st = sbase + c*STAGE_SZ;                                       \
    const char* wg = (const char*)(WSRC) + ((size_t)(bm+lrow)*KCAT + c*KC)*2;     \
    const char* ag = (const char*)(ASRC) + ((size_t)(bn+lrow)*KCAT + c*KC)*2;     \
    _Pragma("unroll")                                                             \
    for (int q=0;q<4;q++){                                                        \
      uint32_t off = sw128_((uint32_t)(lrow*128 + (lseg4+q)*16));                 \
      cp_async16_(st + off, wg + (lseg4+q)*16);                                   \
      cp_async16_(st + STAGE_HALF + off, ag + (lseg4+q)*16);                      \
    }                                                                             \
    CP_COMMIT();                                                                  \
  }                                                                               \
  float acc[4][4][4];                                                             \
  _Pragma("unroll")                                                               \
  for (int i=0;i<4;i++)                                                           \
    _Pragma("unroll")                                                             \
    for (int jj=0;jj<4;jj++)                                                      \
      _Pragma("unroll")                                                           \
      for (int v=0;v<4;v++) acc[i][jj][v]=0.f;                                    \
  const uint32_t a_row = (uint32_t)(lane & 15);                                   \
  const uint32_t a_k16 = (uint32_t)((lane >> 4) * 16);                            \
  const uint32_t b_row = (uint32_t)((lane & 7) + ((lane & 16) >> 1));             \
  const uint32_t b_k16 = (uint32_t)((lane & 8) ? 16 : 0);                         \
  for (int c = 0; c < NCHUNK; c++) {                                              \
    CP_WAIT1();                                                                   \
    __syncthreads();                                                              \
    const uint32_t wbase = sbase + (c & 1)*STAGE_SZ;                              \
    const uint32_t abase = wbase + STAGE_HALF;                                    \
    _Pragma("unroll")                                                             \
    for (int k = 0; k < 4; k++) {                                                 \
      uint32_t af[4][4], bf[2][4];                                                \
      _Pragma("unroll")                                                           \
      for (int mt=0; mt<4; mt++)                                                  \
        ldsm_x4_(af[mt], wbase + sw128_((uint32_t)((wm + mt*16 + a_row)*128) + k*32 + a_k16)); \
      _Pragma("unroll")                                                           \
      for (int nt2=0; nt2<2; nt2++)                                               \
        ldsm_x4_(bf[nt2], abase + sw128_((uint32_t)((wn + nt2*16 + b_row)*128) + k*32 + b_k16)); \
      _Pragma("unroll")                                                           \
      for (int mt=0; mt<4; mt++)                                                  \
        _Pragma("unroll")                                                         \
        for (int nt=0; nt<4; nt++)                                                \
          mma16816_(acc[mt][nt], af[mt], &bf[nt>>1][(nt&1)*2]);                   \
    }                                                                             \
    __syncthreads();                                                              \
    if (c + 2 < NCHUNK) {                                                         \
      const uint32_t st = sbase + (c & 1)*STAGE_SZ;                               \
      const char* wg = (const char*)(WSRC) + ((size_t)(bm+lrow)*KCAT + (c+2)*KC)*2; \
      const char* ag = (const char*)(ASRC) + ((size_t)(bn+lrow)*KCAT + (c+2)*KC)*2; \
      _Pragma("unroll")                                                           \
      for (int q=0;q<4;q++){                                                      \
        uint32_t off = sw128_((uint32_t)(lrow*128 + (lseg4+q)*16));               \
        cp_async16_(st + off, wg + (lseg4+q)*16);                                 \
        cp_async16_(st + STAGE_HALF + off, ag + (lseg4+q)*16);                    \
      }                                                                           \
    }                                                                             \
    CP_COMMIT();                                                                  \
  }                                                                               \
  CP_WAIT0();                                                                     \
  {                                                                               \
    const int mq = lane >> 2;                                                     \
    const int nq = (lane & 3) * 2;                                                \
    _Pragma("unroll")                                                             \
    for (int mt=0; mt<4; mt++)                                                    \
      _Pragma("unroll")                                                           \
      for (int nt=0; nt<4; nt++){                                                 \
        int m0 = wm + mt*16 + mq;                                                 \
        int n0 = wn + nt*8 + nq;                                                  \
        eps[(n0  )*EPS_STRIDE + m0    ] = acc[mt][nt][0];                         \
        eps[(n0+1)*EPS_STRIDE + m0    ] = acc[mt][nt][1];                         \
        eps[(n0  )*EPS_STRIDE + m0 + 8] = acc[mt][nt][2];                         \
        eps[(n0+1)*EPS_STRIDE + m0 + 8] = acc[mt][nt][3];                         \
      }                                                                           \
  }                                                                               \
  __syncthreads();

// ============================================================
// vocab GEMM (R5 exact)
// ============================================================
__global__ void __launch_bounds__(256) out_gemm_mma(
    const float* __restrict__ ob, float* __restrict__ outp)
{
  extern __shared__ __align__(128) char smg[];
  const uint32_t sbase = smem_u32(smg);
  float* eps = (float*)smg;
  const int tid  = threadIdx.x;
  const int wid  = tid >> 5;
  const int lane = tid & 31;
  const int bn = blockIdx.x * 128;
  const int bm = blockIdx.y * 128;
  const int wm = (wid & 1) * 64;
  const int wn = (wid >> 1) * 32;

  MMA_MAINLOOP(g_wcat, g_acat)

  {
    const int mo = (tid & 15) * 8;
    const int vg = bm + mo;
    float4 ob0 = *(const float4*)&ob[vg];
    float4 ob1 = *(const float4*)&ob[vg+4];
    #pragma unroll
    for (int it = 0; it < 8; it++) {
      int n = (tid >> 4) + it*16;
      int r = bn + n;
      if (r < NROWS) {
        const float* ep = eps + n*EPS_STRIDE + mo;
        float4 v0 = *(const float4*)ep;
        float4 v1 = *(const float4*)(ep+4);
        v0.x+=ob0.x; v0.y+=ob0.y; v0.z+=ob0.z; v0.w+=ob0.w;
        v1.x+=ob1.x; v1.y+=ob1.y; v1.z+=ob1.z; v1.w+=ob1.w;
        float* op = outp + (size_t)((r & 7)*STEPS + (r >> 3))*VOCAB + vg;
        *(float4*)op     = v0;
        *(float4*)(op+4) = v1;
      }
    }
  }
}

// ============================================================
// xp1 GEMM (R5 exact)
// ============================================================
__global__ void __launch_bounds__(256) xp_gemm_mma(
    const float* __restrict__ bih, const float* __restrict__ bhh)
{
  extern __shared__ __align__(128) char smg[];
  const uint32_t sbase = smem_u32(smg);
  float* eps = (float*)smg;
  const int tid  = threadIdx.x;
  const int wid  = tid >> 5;
  const int lane = tid & 31;
  const int bn = blockIdx.x * 128;   // data rows
  const int bm = blockIdx.y * 128;   // gate rows (0..1023)
  const int wm = (wid & 1) * 64;
  const int wn = (wid >> 1) * 32;

  MMA_MAINLOOP(g_xw, g_acat)

  {
    const int mo = (tid & 15) * 8;
    const int mg = bm + mo;
    const int gate = bm >> 8;
    const int ub = mg & 255;
    float bb[8];
    #pragma unroll
    for (int q=0;q<8;q++) bb[q] = bih[mg+q] + bhh[mg+q];
    #pragma unroll
    for (int it = 0; it < 8; it++) {
      int n = (tid >> 4) + it*16;
      int r = bn + n;
      if (r < NROWS) {
        const float* ep = eps + n*EPS_STRIDE + mo;
        float* op = g_xp + (size_t)r*G4 + ub*4 + gate;
        #pragma unroll
        for (int q=0;q<8;q++)
          op[q*4] = ep[q] + bb[q];
      }
    }
  }
}

// ============================================================
extern "C" void kernel_launch(void* const* d_in, const int* in_sizes, int n_in,
                              void* d_out, int out_size) {
  const float* thought = (const float*)d_in[0];
  const int*   captions= (const int*)  d_in[1];
  const float* emb_w   = (const float*)d_in[2];
  const float* w_ih0   = (const float*)d_in[3];
  const float* w_hh0   = (const float*)d_in[4];
  const float* b_ih0   = (const float*)d_in[5];
  const float* b_hh0   = (const float*)d_in[6];
  const float* w_ih1   = (const float*)d_in[7];
  const float* w_hh1   = (const float*)d_in[8];
  const float* b_ih1   = (const float*)d_in[9];
  const float* b_hh1   = (const float*)d_in[10];
  const float* gw1     = (const float*)d_in[11];
  const float* gb1     = (const float*)d_in[12];
  const float* gw2     = (const float*)d_in[13];
  const float* gb2     = (const float*)d_in[14];
  const float* ow      = (const float*)d_in[15];
  const float* ob      = (const float*)d_in[16];
  float* outp = (float*)d_out;

  static cudaStream_t s1 = nullptr;
  static cudaEvent_t ev0 = nullptr, ev1 = nullptr;
  if (!s1) {
    cudaStreamCreate(&s1);
    cudaEventCreateWithFlags(&ev0, cudaEventDisableTiming);
    cudaEventCreateWithFlags(&ev1, cudaEventDisableTiming);
    cudaFuncSetAttribute(out_gemm_mma, cudaFuncAttributeMaxDynamicSharedMemorySize, GSMEM);
    cudaFuncSetAttribute(xp_gemm_mma,  cudaFuncAttributeMaxDynamicSharedMemorySize, GSMEM);
  }

  // fork: weight conversions overlap xp0 + scan0 (R5 layout)
  cudaEventRecord(ev0, 0);
  cudaStreamWaitEvent(s1, ev0, 0);
  wihcvt_kernel<<<G4, 256, 0, s1>>>(w_ih1);
  wcat_kernel<<<VOCAB, 256, 0, s1>>>(ow);
  cudaEventRecord(ev1, s1);

  xp0_kernel<<<STEPS, 256>>>(captions, emb_w, w_ih0, b_ih0, b_hh0);
  lstm_scan2<<<64, 256>>>(w_hh0, thought, 0);
  h1cvt_kernel<<<NPAD, 256>>>();
  cudaStreamWaitEvent(0, ev1, 0);   // join before consumers of g_xw / g_wcat
  {
    dim3 gx(NPAD/128, G4/128);                    // (32, 8)
    xp_gemm_mma<<<gx, 256, GSMEM>>>(b_ih1, b_hh1);
  }
  lstm_scan2<<<64, 256>>>(w_hh1, thought, 1);
  gateacat_kernel<<<512, 256>>>(gw1, gb1, gw2, gb2);
  dim3 gg(NPAD/128, VOCAB/128);                   // (32, 250)
  out_gemm_mma<<<gg, 256, GSMEM>>>(ob, outp);
}